// round 9
// baseline (speedup 1.0000x reference)
#include <cuda_runtime.h>

#define BZ 32
#define TT 1024
#define DD 1024
#define KK 8
#define EE 400
#define ESPLIT 16
#define ECHUNK 25    // EE / ESPLIT

// Scratch (static device globals: no allocation APIs).
__device__ float g_temp4[ESPLIT * BZ * KK * DD];  // 16 MB: per-E-chunk partials
__device__ float g_temp [BZ * KK * DD];           // 1 MB: reduced temp[b][k][d]

// ---------------------------------------------------------------------------
// Kernel 1: temp partials. temp4[z][b][k][d] = sum_{e in chunk z} S[b,e,k]*W[e,d]
// Grid (2, B/2, 16) = 512 blocks, 128 threads.
// Thread owns a d-QUAD (one coalesced LDG.128 of W per e) for a b-PAIR and
// all 8 k -> per e: 1 LDG.128 + 8 broadcast LDS.128 + 32 fma.rn.f32x2
// (78% FMA density; R6 version was 59% and latency-starved at 18% issue).
// S values pre-duplicated ((s,s) in 64-bit words) in shared. Plain stores.
// ---------------------------------------------------------------------------
__global__ void __launch_bounds__(128) temp_partial_kernel(
    const float* __restrict__ S,    // [B, E, K]
    const float* __restrict__ W)    // [E, D]
{
    const int tid = threadIdx.x;
    const int b0  = blockIdx.y * 2;
    const int z   = blockIdx.z;
    const int e0  = z * ECHUNK;
    const int d0  = blockIdx.x * 512 + tid * 4;

    __shared__ unsigned long long S_dup[2][ECHUNK * KK];   // 3.2 KB
    for (int i = tid; i < 2 * ECHUNK * KK; i += 128) {
        const int bsel = i / (ECHUNK * KK);
        const int j    = i % (ECHUNK * KK);
        const float s = S[(size_t)(b0 + bsel) * EE * KK + (size_t)e0 * KK + j];
        unsigned long long p;
        asm("mov.b64 %0, {%1, %1};" : "=l"(p) : "f"(s));
        S_dup[bsel][j] = p;
    }
    __syncthreads();

    // acc[b][k] = (f32x2 lo-pair, f32x2 hi-pair) for this thread's d-quad.
    unsigned long long acc[2][KK][2];
    #pragma unroll
    for (int b = 0; b < 2; b++)
        #pragma unroll
        for (int k = 0; k < KK; k++) { acc[b][k][0] = 0ULL; acc[b][k][1] = 0ULL; }

    #pragma unroll 5
    for (int e = 0; e < ECHUNK; e++) {
        const float4 w = *reinterpret_cast<const float4*>(W + (size_t)(e0 + e) * DD + d0);
        unsigned long long w2a, w2b;
        asm("mov.b64 %0, {%1, %2};" : "=l"(w2a) : "f"(w.x), "f"(w.y));
        asm("mov.b64 %0, {%1, %2};" : "=l"(w2b) : "f"(w.z), "f"(w.w));
        #pragma unroll
        for (int b = 0; b < 2; b++) {
            const ulonglong2* sp =
                reinterpret_cast<const ulonglong2*>(&S_dup[b][e * KK]);
            #pragma unroll
            for (int k2 = 0; k2 < 4; k2++) {
                const ulonglong2 s2 = sp[k2];   // dup-pairs for k=2*k2, 2*k2+1
                asm("fma.rn.f32x2 %0, %1, %2, %0;" : "+l"(acc[b][2*k2  ][0]) : "l"(w2a), "l"(s2.x));
                asm("fma.rn.f32x2 %0, %1, %2, %0;" : "+l"(acc[b][2*k2  ][1]) : "l"(w2b), "l"(s2.x));
                asm("fma.rn.f32x2 %0, %1, %2, %0;" : "+l"(acc[b][2*k2+1][0]) : "l"(w2a), "l"(s2.y));
                asm("fma.rn.f32x2 %0, %1, %2, %0;" : "+l"(acc[b][2*k2+1][1]) : "l"(w2b), "l"(s2.y));
            }
        }
    }

    // Bits of (lo,hi) f32x2 pairs ARE the 4 packed floats: store as 128-bit.
    #pragma unroll
    for (int b = 0; b < 2; b++) {
        #pragma unroll
        for (int k = 0; k < KK; k++) {
            ulonglong2 o; o.x = acc[b][k][0]; o.y = acc[b][k][1];
            *reinterpret_cast<ulonglong2*>(
                g_temp4 + (((size_t)z * BZ + (b0 + b)) * KK + k) * DD + d0) = o;
        }
    }
}

// ---------------------------------------------------------------------------
// Kernel 2: reduce the 16 E-chunk partials into g_temp, and zero `out`.
// 256 blocks x 256 threads = 65536 threads; thread owns ONE float4 of g_temp
// AND zeroes ONE float4 of out (65536*4 = 262144 floats = B*T*K, full output).
// ---------------------------------------------------------------------------
__global__ void __launch_bounds__(256) temp_reduce_kernel(float* __restrict__ out)
{
    const int i = blockIdx.x * 256 + threadIdx.x;            // float4 index
    const float4* src = reinterpret_cast<const float4*>(g_temp4);
    float4 a = src[i];
    #pragma unroll
    for (int z = 1; z < ESPLIT; z++) {
        const float4 t = src[(size_t)z * (BZ * KK * DD / 4) + i];
        a.x += t.x; a.y += t.y; a.z += t.z; a.w += t.w;
    }
    reinterpret_cast<float4*>(g_temp)[i] = a;
    reinterpret_cast<float4*>(out)[i] = make_float4(0.f, 0.f, 0.f, 0.f);
}

// ---------------------------------------------------------------------------
// Kernel 3 (main, HBM-bound): q[b,t,k] = dot(temp[b,k,:], h[b,t,:]) folded
// into the segment sum via atomicAdd. (Unchanged from R6: ~25us, near the
// ~21us DRAM floor; will revisit with profile evidence.)
// ---------------------------------------------------------------------------
__global__ void __launch_bounds__(128) main_kernel(
    const float* __restrict__ hidden,   // [B, T, D]
    const int*   __restrict__ labels,   // [B, T]
    const int*   __restrict__ pB,
    const int*   __restrict__ pI,
    float* __restrict__ out)            // [B, T, K], zeroed by temp_reduce
{
    const int tid   = threadIdx.x;
    const int b     = blockIdx.y;
    const int tok0  = blockIdx.x * 64;
    const int warp  = tid >> 5;
    const int lane  = tid & 31;
    const int slice = blockIdx.z * 4 + warp;     // 0..7
    const int d0    = slice * 128 + lane * 4;

    __shared__ int seg_sh[64];
    __shared__ int wsum[4];

    // ---- in-block span-id scan over all 1024 tokens of batch b ----
    {
        const int Bi = pB ? *pB : 1;
        const int Ii = pI ? *pI : 2;
        const int4* lb = reinterpret_cast<const int4*>(labels + b * TT);
        const int4 pa  = lb[tid * 2];
        const int4 pb4 = lb[tid * 2 + 1];
        int l[8] = {pa.x, pa.y, pa.z, pa.w, pb4.x, pb4.y, pb4.z, pb4.w};

        int cnt = 0;
        #pragma unroll
        for (int j = 0; j < 8; j++) cnt += (l[j] == Bi);

        int incl = cnt;
        #pragma unroll
        for (int o = 1; o < 32; o <<= 1) {
            const int u = __shfl_up_sync(0xFFFFFFFFu, incl, o);
            if (lane >= o) incl += u;
        }
        if (lane == 31) wsum[warp] = incl;
        __syncthreads();

        int base = 0;
        #pragma unroll
        for (int wv = 0; wv < 4; wv++) base += (wv < warp) ? wsum[wv] : 0;

        int run = base + incl - cnt;     // exclusive B-count before token tid*8
        #pragma unroll
        for (int j = 0; j < 8; j++) {
            const int isB = (l[j] == Bi);
            run += isB;
            const int span  = run - 1;
            const bool valid = (isB | (l[j] == Ii)) && span >= 0;
            const int tokg = tid * 8 + j;
            if ((unsigned)(tokg - tok0) < 64u)
                seg_sh[tokg - tok0] = valid ? span : -1;
        }
    }
    __syncthreads();

    // temp slice in registers: 8 float4 = 32 regs, read once from L2.
    float4 ta[KK];
    #pragma unroll
    for (int k = 0; k < KK; k++)
        ta[k] = *reinterpret_cast<const float4*>(
            g_temp + ((size_t)b * KK + k) * DD + d0);

    const float* hb = hidden + ((size_t)b * TT + tok0) * DD + d0;
    float* const ob = out + (size_t)b * TT * KK + (lane & 7);
    const int myt = lane >> 3;

    #pragma unroll 1
    for (int g = 0; g < 64; g += 4) {
        // 4 independent coalesced LDG.128 (evict-first: hidden read once).
        float4 h[4];
        #pragma unroll
        for (int t = 0; t < 4; t++)
            h[t] = __ldcs(reinterpret_cast<const float4*>(hb + (size_t)(g + t) * DD));

        float v[32];   // v[t*8+k] = this lane's 4-float partial dot
        #pragma unroll
        for (int k = 0; k < KK; k++) {
            #pragma unroll
            for (int t = 0; t < 4; t++) {
                float a;
                a = h[t].x * ta[k].x;
                a = fmaf(h[t].y, ta[k].y, a);
                a = fmaf(h[t].z, ta[k].z, a);
                a = fmaf(h[t].w, ta[k].w, a);
                v[t * 8 + k] = a;
            }
        }

        // Butterfly-halving all-reduce: 32 values x 32 lanes; the fully
        // reduced value index == lane after steps m=16..1.
        #pragma unroll
        for (int m = 16; m >= 1; m >>= 1) {
            const bool up = (lane & m) != 0;
            #pragma unroll
            for (int i = 0; i < m; i++) {
                float send = up ? v[i] : v[i + m];
                float recv = __shfl_xor_sync(0xFFFFFFFFu, send, m);
                v[i] = (up ? v[i + m] : v[i]) + recv;
            }
        }

        const int s = seg_sh[g + myt];
        if (s >= 0)
            atomicAdd(ob + (size_t)s * KK, v[0]);
    }
}

// ---------------------------------------------------------------------------
extern "C" void kernel_launch(void* const* d_in, const int* in_sizes, int n_in,
                              void* d_out, int out_size)
{
    const float* hidden = (const float*)d_in[0];   // [32,1024,1024] f32
    const float* slot   = (const float*)d_in[1];   // [32,400,8]     f32
    const float* W      = (const float*)d_in[2];   // [400,1024]     f32
    const int*   labels = (const int*)  d_in[3];   // [32,1024]      i32
    const int*   pB     = (n_in > 4) ? (const int*)d_in[4] : nullptr;
    const int*   pI     = (n_in > 5) ? (const int*)d_in[5] : nullptr;
    float* out = (float*)d_out;

    (void)in_sizes; (void)out_size;

    temp_partial_kernel<<<dim3(2, BZ / 2, ESPLIT), 128>>>(slot, W);
    temp_reduce_kernel <<<BZ * KK * DD / 4 / 256, 256>>>(out);
    main_kernel        <<<dim3(TT / 64, BZ, 2), 128>>>(hidden, labels, pB, pI, out);
}